// round 7
// baseline (speedup 1.0000x reference)
#include <cuda_runtime.h>
#include <string.h>

#define BATCH 128
#define TLEN  8192
#define HDIM  96
#define NTHR  416   // 12 gate warps + 1 output warp; CTA runs TWO batch elements

// Packed fp32x2 FMA (Blackwell).
#define FMA2(d, a, b, c) \
    asm("fma.rn.f32x2 %0, %1, %2, %3;" : "=l"(d) : "l"(a), "l"(b), "l"(c))
#define ADD2(d, a, b) \
    asm("add.rn.f32x2 %0, %1, %2;" : "=l"(d) : "l"(a), "l"(b))
#define UNPACK2(lo, hi, v) \
    asm("mov.b64 {%0, %1}, %2;" : "=f"(lo), "=f"(hi) : "l"(v))

__device__ __forceinline__ float ex2_fast(float x) {
    float y; asm("ex2.approx.f32 %0, %1;" : "=f"(y) : "f"(x)); return y;
}
__device__ __forceinline__ float rcp_fast(float x) {
    float y; asm("rcp.approx.f32 %0, %1;" : "=f"(y) : "f"(x)); return y;
}
__device__ __forceinline__ void cta_bar() {
    asm volatile("bar.sync 0;" ::: "memory");
}

#define LOG2E 1.4426950408889634f

// fused dual-element LSTM step: element B's independent work hides element A's
// serial tail (butterfly shfls, MUFU act, c/h chain) within the same warp.
__device__ __forceinline__ void lstm_step2(
    const float* __restrict__ hinA, float* __restrict__ houtA,
    const float* __restrict__ hinB, float* __restrict__ houtB,
    float xA, float xB,
    const ulonglong2 (&wreg)[4][6], float wi, float bias, float mq,
    int base, int b0, int b1, int u, float& cA, float& cB)
{
    const ulonglong2* ha = (const ulonglong2*)hinA;   // already offset by 24q
    const ulonglong2* hb = (const ulonglong2*)hinB;
    // front-load both h quarters (MLP)
    ulonglong2 hA0 = ha[0], hA1 = ha[1], hA2 = ha[2];
    ulonglong2 hA3 = ha[3], hA4 = ha[4], hA5 = ha[5];
    ulonglong2 hB0 = hb[0], hB1 = hb[1], hB2 = hb[2];
    ulonglong2 hB3 = hb[3], hB4 = hb[4], hB5 = hb[5];
    float preA = fmaf(xA, wi, bias);
    float preB = fmaf(xB, wi, bias);

    unsigned long long accA[4][2], accB[4][2];
    #pragma unroll
    for (int g = 0; g < 4; g++) {
        accA[g][0] = 0ull; accA[g][1] = 0ull;
        accB[g][0] = 0ull; accB[g][1] = 0ull;
    }
    #pragma unroll
    for (int g = 0; g < 4; g++) {
        FMA2(accA[g][0], wreg[g][0].x, hA0.x, accA[g][0]);
        FMA2(accA[g][1], wreg[g][0].y, hA0.y, accA[g][1]);
        FMA2(accB[g][0], wreg[g][0].x, hB0.x, accB[g][0]);
        FMA2(accB[g][1], wreg[g][0].y, hB0.y, accB[g][1]);
        FMA2(accA[g][0], wreg[g][1].x, hA1.x, accA[g][0]);
        FMA2(accA[g][1], wreg[g][1].y, hA1.y, accA[g][1]);
        FMA2(accB[g][0], wreg[g][1].x, hB1.x, accB[g][0]);
        FMA2(accB[g][1], wreg[g][1].y, hB1.y, accB[g][1]);
        FMA2(accA[g][0], wreg[g][2].x, hA2.x, accA[g][0]);
        FMA2(accA[g][1], wreg[g][2].y, hA2.y, accA[g][1]);
        FMA2(accB[g][0], wreg[g][2].x, hB2.x, accB[g][0]);
        FMA2(accB[g][1], wreg[g][2].y, hB2.y, accB[g][1]);
        FMA2(accA[g][0], wreg[g][3].x, hA3.x, accA[g][0]);
        FMA2(accA[g][1], wreg[g][3].y, hA3.y, accA[g][1]);
        FMA2(accB[g][0], wreg[g][3].x, hB3.x, accB[g][0]);
        FMA2(accB[g][1], wreg[g][3].y, hB3.y, accB[g][1]);
        FMA2(accA[g][0], wreg[g][4].x, hA4.x, accA[g][0]);
        FMA2(accA[g][1], wreg[g][4].y, hA4.y, accA[g][1]);
        FMA2(accB[g][0], wreg[g][4].x, hB4.x, accB[g][0]);
        FMA2(accB[g][1], wreg[g][4].y, hB4.y, accB[g][1]);
        FMA2(accA[g][0], wreg[g][5].x, hA5.x, accA[g][0]);
        FMA2(accA[g][1], wreg[g][5].y, hA5.y, accA[g][1]);
        FMA2(accB[g][0], wreg[g][5].x, hB5.x, accB[g][0]);
        FMA2(accB[g][1], wreg[g][5].y, hB5.y, accB[g][1]);
    }
    float pgA[4], pgB[4];
    #pragma unroll
    for (int g = 0; g < 4; g++) {
        unsigned long long sA, sB;
        ADD2(sA, accA[g][0], accA[g][1]);
        ADD2(sB, accB[g][0], accB[g][1]);
        float loA, hiA, loB, hiB;
        UNPACK2(loA, hiA, sA);
        UNPACK2(loB, hiB, sB);
        pgA[g] = loA + hiA;
        pgB[g] = loB + hiB;
    }

    // butterflies (A and B interleaved; independent chains)
    float keepA1 = b0 ? pgA[1] : pgA[0];
    float sendA1 = b0 ? pgA[0] : pgA[1];
    float keepA2 = b0 ? pgA[3] : pgA[2];
    float sendA2 = b0 ? pgA[2] : pgA[3];
    float keepB1 = b0 ? pgB[1] : pgB[0];
    float sendB1 = b0 ? pgB[0] : pgB[1];
    float keepB2 = b0 ? pgB[3] : pgB[2];
    float sendB2 = b0 ? pgB[2] : pgB[3];
    keepA1 += __shfl_xor_sync(0xffffffffu, sendA1, 1);
    keepA2 += __shfl_xor_sync(0xffffffffu, sendA2, 1);
    keepB1 += __shfl_xor_sync(0xffffffffu, sendB1, 1);
    keepB2 += __shfl_xor_sync(0xffffffffu, sendB2, 1);
    float keepA = b1 ? keepA2 : keepA1;
    float sendA = b1 ? keepA1 : keepA2;
    float keepB = b1 ? keepB2 : keepB1;
    float sendB = b1 ? keepB1 : keepB2;
    float zA = keepA + __shfl_xor_sync(0xffffffffu, sendA, 2) + preA;
    float zB = keepB + __shfl_xor_sync(0xffffffffu, sendB, 2) + preB;

    // activations: 1 - mq/(2^z + 1)
    float eA = ex2_fast(zA);
    float eB = ex2_fast(zB);
    float rA = rcp_fast(eA + 1.0f);
    float rB = rcp_fast(eB + 1.0f);
    float actA = fmaf(-mq, rA, 1.0f);
    float actB = fmaf(-mq, rB, 1.0f);

    // gather all 4 activations to all sublanes (redundant branchless update)
    float iA = __shfl_sync(0xffffffffu, actA, base);
    float fA = __shfl_sync(0xffffffffu, actA, base + 1);
    float gA = __shfl_sync(0xffffffffu, actA, base + 2);
    float oA = __shfl_sync(0xffffffffu, actA, base + 3);
    float iB = __shfl_sync(0xffffffffu, actB, base);
    float fB = __shfl_sync(0xffffffffu, actB, base + 1);
    float gB = __shfl_sync(0xffffffffu, actB, base + 2);
    float oB = __shfl_sync(0xffffffffu, actB, base + 3);

    cA = fmaf(fA, cA, iA * gA);
    cB = fmaf(fB, cB, iB * gB);
    float e2A = ex2_fast(cA * (2.0f * LOG2E));
    float e2B = ex2_fast(cB * (2.0f * LOG2E));
    float hA = oA * fmaf(-2.0f, rcp_fast(e2A + 1.0f), 1.0f);
    float hB = oB * fmaf(-2.0f, rcp_fast(e2B + 1.0f), 1.0f);
    houtA[u] = hA;   // 4 sublanes store identical value (benign)
    houtB[u] = hB;
}

__global__ void __launch_bounds__(NTHR, 1)
lstm_persistent_kernel(const float* __restrict__ x,
                       const float* __restrict__ w_ih,
                       const float* __restrict__ w_hh,
                       const float* __restrict__ b_ih,
                       const float* __restrict__ b_hh,
                       const float* __restrict__ w_out,
                       const float* __restrict__ b_out,
                       float* __restrict__ out)
{
    __shared__ __align__(16) float h_s[2][2][HDIM];   // [elem][phase][H]

    const int tid  = threadIdx.x;
    const int wid  = tid >> 5;
    const int lane = tid & 31;

    const int bA = blockIdx.x * 2;
    const int bB = bA + 1;
    const float* xrowA = x + (size_t)bA * TLEN;
    const float* xrowB = x + (size_t)bB * TLEN;

    if (tid < 2 * 2 * HDIM) ((float*)h_s)[tid] = 0.0f;

    const bool is_gate = (wid < 12);
    const int u = 8 * wid + (lane >> 2);
    const int q = lane & 3;

    ulonglong2 wreg[4][6];
    float wi = 0.0f, bias = 0.0f;
    if (is_gate) {
        #pragma unroll
        for (int g = 0; g < 4; g++) {
            const float sg = (g == 2) ? 2.0f * LOG2E : LOG2E;
            const float4* wr = (const float4*)(w_hh + (size_t)(g * HDIM + u) * HDIM + 24 * q);
            #pragma unroll
            for (int j = 0; j < 6; j++) {
                float4 t = wr[j];
                t.x *= sg; t.y *= sg; t.z *= sg; t.w *= sg;
                ulonglong2 pk;
                memcpy(&pk, &t, 16);
                wreg[g][j] = pk;
            }
        }
        const float sq = (q == 2) ? 2.0f * LOG2E : LOG2E;
        const int row = q * HDIM + u;
        wi   = w_ih[row] * sq;
        bias = (b_ih[row] + b_hh[row]) * sq;
    }
    const float mq = (q == 2) ? 2.0f : 1.0f;
    const int  base = lane & ~3;
    const int  b0 = lane & 1, b1 = lane & 2;

    __syncthreads();   // h init + weights visible

    if (is_gate) {
        const float* hinA0 = h_s[0][0] + 24 * q;
        const float* hinA1 = h_s[0][1] + 24 * q;
        const float* hinB0 = h_s[1][0] + 24 * q;
        const float* hinB1 = h_s[1][1] + 24 * q;
        float cA = 0.0f, cB = 0.0f;
        float xA = __ldg(xrowA), xB = __ldg(xrowB);
        #pragma unroll 1
        for (int t = 0; t < TLEN; t += 2) {
            float xA1 = __ldg(xrowA + t + 1);
            float xB1 = __ldg(xrowB + t + 1);
            lstm_step2(hinA0, h_s[0][1], hinB0, h_s[1][1], xA, xB,
                       wreg, wi, bias, mq, base, b0, b1, u, cA, cB);
            cta_bar();
            int t2 = (t + 2 < TLEN) ? t + 2 : t;   // clamp tail prefetch
            xA = __ldg(xrowA + t2);
            xB = __ldg(xrowB + t2);
            lstm_step2(hinA1, h_s[0][0], hinB1, h_s[1][0], xA1, xB1,
                       wreg, wi, bias, mq, base, b0, b1, u, cA, cB);
            cta_bar();
        }
    } else {
        // ---------------- output warp: y for both elements ----------------
        float wo0 = w_out[lane];
        float wo1 = w_out[lane + 32];
        float wo2 = w_out[lane + 64];
        float bo  = b_out[0];
        float* outA = out + (size_t)bA * TLEN;
        float* outB = out + (size_t)bB * TLEN;

        cta_bar();   // t = 0: nothing to emit yet
        #pragma unroll 1
        for (int t = 1; t < TLEN; t++) {
            const float* hpA = h_s[0][t & 1];   // h(t-1)
            const float* hpB = h_s[1][t & 1];
            float pA = hpA[lane] * wo0 + hpA[lane + 32] * wo1 + hpA[lane + 64] * wo2;
            float pB = hpB[lane] * wo0 + hpB[lane + 32] * wo1 + hpB[lane + 64] * wo2;
            #pragma unroll
            for (int s = 16; s >= 1; s >>= 1) {
                pA += __shfl_xor_sync(0xffffffffu, pA, s);
                pB += __shfl_xor_sync(0xffffffffu, pB, s);
            }
            if (lane == 0) { outA[t - 1] = pA + bo; outB[t - 1] = pB + bo; }
            cta_bar();
        }
        // final y(T-1): phase 0 (TLEN even)
        const float* hpA = h_s[0][0];
        const float* hpB = h_s[1][0];
        float pA = hpA[lane] * wo0 + hpA[lane + 32] * wo1 + hpA[lane + 64] * wo2;
        float pB = hpB[lane] * wo0 + hpB[lane + 32] * wo1 + hpB[lane + 64] * wo2;
        #pragma unroll
        for (int s = 16; s >= 1; s >>= 1) {
            pA += __shfl_xor_sync(0xffffffffu, pA, s);
            pB += __shfl_xor_sync(0xffffffffu, pB, s);
        }
        if (lane == 0) { outA[TLEN - 1] = pA + bo; outB[TLEN - 1] = pB + bo; }
    }
}

extern "C" void kernel_launch(void* const* d_in, const int* in_sizes, int n_in,
                              void* d_out, int out_size)
{
    const float* x     = (const float*)d_in[0];
    const float* w_ih  = (const float*)d_in[1];
    const float* w_hh  = (const float*)d_in[2];
    const float* b_ih  = (const float*)d_in[3];
    const float* b_hh  = (const float*)d_in[4];
    const float* w_out = (const float*)d_in[5];
    const float* b_out = (const float*)d_in[6];
    float* out = (float*)d_out;

    lstm_persistent_kernel<<<BATCH / 2, NTHR>>>(x, w_ih, w_hh, b_ih, b_hh,
                                                w_out, b_out, out);
}

// round 8
// speedup vs baseline: 1.6459x; 1.6459x over previous
#include <cuda_runtime.h>
#include <string.h>

#define BATCH 128
#define TLEN  8192
#define HDIM  96
#define NTHR  416   // 12 gate warps + 1 output warp

// Packed fp32x2 FMA (Blackwell).
#define FMA2(d, a, b, c) \
    asm("fma.rn.f32x2 %0, %1, %2, %3;" : "=l"(d) : "l"(a), "l"(b), "l"(c))
#define ADD2(d, a, b) \
    asm("add.rn.f32x2 %0, %1, %2;" : "=l"(d) : "l"(a), "l"(b))
#define UNPACK2(lo, hi, v) \
    asm("mov.b64 {%0, %1}, %2;" : "=f"(lo), "=f"(hi) : "l"(v))

__device__ __forceinline__ float ex2_fast(float x) {
    float y; asm("ex2.approx.f32 %0, %1;" : "=f"(y) : "f"(x)); return y;
}
__device__ __forceinline__ float rcp_fast(float x) {
    float y; asm("rcp.approx.f32 %0, %1;" : "=f"(y) : "f"(x)); return y;
}
__device__ __forceinline__ void cta_bar() {
    asm volatile("bar.sync 0;" ::: "memory");
}

#define LOG2E 1.4426950408889634f

// one LSTM step, full-row lane: lane owns gate q of unit u over ALL 96 columns.
// Gate sum materializes in-lane (no butterfly); gathers + redundant update follow.
__device__ __forceinline__ void lstm_step(
    const float* __restrict__ hin, float* __restrict__ hout, float xt,
    const ulonglong2 (&wreg)[24], float wi, float bias, float mq,
    int base, int u, float& c)
{
    const ulonglong2* h2 = (const ulonglong2*)hin;   // broadcast reads (N=1)
    float pre = fmaf(xt, wi, bias);

    unsigned long long a0 = 0ull, a1 = 0ull, a2 = 0ull, a3 = 0ull;
    #pragma unroll
    for (int i = 0; i < 24; i += 2) {
        ulonglong2 hv0 = h2[i];
        FMA2(a0, wreg[i].x,     hv0.x, a0);
        FMA2(a1, wreg[i].y,     hv0.y, a1);
        ulonglong2 hv1 = h2[i + 1];
        FMA2(a2, wreg[i + 1].x, hv1.x, a2);
        FMA2(a3, wreg[i + 1].y, hv1.y, a3);
    }
    ADD2(a0, a0, a1);
    ADD2(a2, a2, a3);
    ADD2(a0, a0, a2);
    float lo, hi;
    UNPACK2(lo, hi, a0);
    float z = pre + lo + hi;

    // branchless activation in log2 domain: 1 - mq/(2^z + 1)
    float e   = ex2_fast(z);
    float r   = rcp_fast(e + 1.0f);
    float act = fmaf(-mq, r, 1.0f);

    // gather all 4 activations of this unit (parallel shfls)
    float iv = __shfl_sync(0xffffffffu, act, base);
    float fv = __shfl_sync(0xffffffffu, act, base + 1);
    float gv = __shfl_sync(0xffffffffu, act, base + 2);
    float ov = __shfl_sync(0xffffffffu, act, base + 3);

    // redundant branchless update: all 4 sublanes compute identical c, h
    c = fmaf(fv, c, iv * gv);
    float e2 = ex2_fast(c * (2.0f * LOG2E));
    float hc = ov * fmaf(-2.0f, rcp_fast(e2 + 1.0f), 1.0f);
    hout[u] = hc;   // 4 sublanes store the same value to the same address (benign)
}

__global__ void __launch_bounds__(NTHR, 1)
lstm_persistent_kernel(const float* __restrict__ x,
                       const float* __restrict__ w_ih,
                       const float* __restrict__ w_hh,
                       const float* __restrict__ b_ih,
                       const float* __restrict__ b_hh,
                       const float* __restrict__ w_out,
                       const float* __restrict__ b_out,
                       float* __restrict__ out)
{
    __shared__ __align__(16) float x_s[TLEN];      // 32 KB: whole input row
    __shared__ __align__(16) float h_s[2][HDIM];   // ping-pong hidden state

    const int tid  = threadIdx.x;
    const int b    = blockIdx.x;
    const int wid  = tid >> 5;
    const int lane = tid & 31;

    {   // stage whole x row, coalesced float4
        const float4* xg = (const float4*)(x + (size_t)b * TLEN);
        float4* xs = (float4*)x_s;
        for (int i = tid; i < TLEN / 4; i += NTHR) xs[i] = xg[i];
    }
    if (tid < HDIM) { h_s[0][tid] = 0.0f; h_s[1][tid] = 0.0f; }

    const bool is_gate = (wid < 12);
    const int u = 8 * wid + (lane >> 2);   // hidden unit 0..95
    const int q = lane & 3;                // gate id: 0=i 1=f 2=g 3=o

    // Full W_hh row for (gate q, unit u), prescaled into the log2 domain.
    ulonglong2 wreg[24];
    float wi = 0.0f, bias = 0.0f;
    if (is_gate) {
        const float sq = (q == 2) ? 2.0f * LOG2E : LOG2E;
        const int row = q * HDIM + u;
        const float4* wr = (const float4*)(w_hh + (size_t)row * HDIM);
        #pragma unroll
        for (int j = 0; j < 24; j++) {
            float4 t = wr[j];
            t.x *= sq; t.y *= sq; t.z *= sq; t.w *= sq;
            ulonglong2 pk;
            memcpy(&pk, &t, 16);
            wreg[j] = pk;
        }
        wi   = w_ih[row] * sq;
        bias = (b_ih[row] + b_hh[row]) * sq;
    }
    const float mq = (q == 2) ? 2.0f : 1.0f;
    const int  base = lane & ~3;

    float* outrow = out + (size_t)b * TLEN;

    __syncthreads();   // x_s, h init, weights ready (convergent)

    if (is_gate) {
        // ---------------- gate warps: uniform loop, no per-step branches -------
        float c = 0.0f;
        #pragma unroll 1
        for (int t = 0; t < TLEN; t += 2) {
            lstm_step(h_s[0], h_s[1], x_s[t],     wreg, wi, bias, mq, base, u, c);
            cta_bar();
            lstm_step(h_s[1], h_s[0], x_s[t + 1], wreg, wi, bias, mq, base, u, c);
            cta_bar();
        }
    } else {
        // ---------------- output warp: its own uniform loop -------------------
        float wo0 = w_out[lane];
        float wo1 = w_out[lane + 32];
        float wo2 = w_out[lane + 64];
        float bo  = b_out[0];

        cta_bar();   // t = 0: nothing to emit yet
        #pragma unroll 1
        for (int t = 1; t < TLEN; t++) {
            const float* hprev = h_s[t & 1];   // h(t-1)
            float part = hprev[lane] * wo0 + hprev[lane + 32] * wo1
                       + hprev[lane + 64] * wo2;
            part += __shfl_xor_sync(0xffffffffu, part, 16);
            part += __shfl_xor_sync(0xffffffffu, part, 8);
            part += __shfl_xor_sync(0xffffffffu, part, 4);
            part += __shfl_xor_sync(0xffffffffu, part, 2);
            part += __shfl_xor_sync(0xffffffffu, part, 1);
            if (lane == 0) outrow[t - 1] = part + bo;
            cta_bar();
        }
        // final y(T-1): h(T-1) lives in h_s[0] (TLEN even)
        const float* hlast = h_s[0];
        float part = hlast[lane] * wo0 + hlast[lane + 32] * wo1
                   + hlast[lane + 64] * wo2;
        part += __shfl_xor_sync(0xffffffffu, part, 16);
        part += __shfl_xor_sync(0xffffffffu, part, 8);
        part += __shfl_xor_sync(0xffffffffu, part, 4);
        part += __shfl_xor_sync(0xffffffffu, part, 2);
        part += __shfl_xor_sync(0xffffffffu, part, 1);
        if (lane == 0) outrow[TLEN - 1] = part + bo;
    }
}

extern "C" void kernel_launch(void* const* d_in, const int* in_sizes, int n_in,
                              void* d_out, int out_size)
{
    const float* x     = (const float*)d_in[0];
    const float* w_ih  = (const float*)d_in[1];
    const float* w_hh  = (const float*)d_in[2];
    const float* b_ih  = (const float*)d_in[3];
    const float* b_hh  = (const float*)d_in[4];
    const float* w_out = (const float*)d_in[5];
    const float* b_out = (const float*)d_in[6];
    float* out = (float*)d_out;

    lstm_persistent_kernel<<<BATCH, NTHR>>>(x, w_ih, w_hh, b_ih, b_hh,
                                            w_out, b_out, out);
}

// round 9
// speedup vs baseline: 1.8652x; 1.1332x over previous
#include <cuda_runtime.h>
#include <string.h>

#define BATCH 128
#define TLEN  8192
#define HDIM  96
#define NTHR  416   // 12 gate warps + 1 output warp

#define FMA2(d, a, b, c) \
    asm("fma.rn.f32x2 %0, %1, %2, %3;" : "=l"(d) : "l"(a), "l"(b), "l"(c))
#define ADD2(d, a, b) \
    asm("add.rn.f32x2 %0, %1, %2;" : "=l"(d) : "l"(a), "l"(b))
#define UNPACK2(lo, hi, v) \
    asm("mov.b64 {%0, %1}, %2;" : "=f"(lo), "=f"(hi) : "l"(v))

__device__ __forceinline__ float ex2_fast(float x) {
    float y; asm("ex2.approx.f32 %0, %1;" : "=f"(y) : "f"(x)); return y;
}
__device__ __forceinline__ float rcp_fast(float x) {
    float y; asm("rcp.approx.f32 %0, %1;" : "=f"(y) : "f"(x)); return y;
}
__device__ __forceinline__ void cta_bar() {
    asm volatile("bar.sync 0;" ::: "memory");
}
// predicated single-lane shared store: no BSSY/BSYNC, 8 conflict-free lanes/warp
__device__ __forceinline__ void sts_pred(int pred_q, unsigned addr, float v) {
    asm volatile(
        "{ .reg .pred p; setp.eq.s32 p, %0, 0; @p st.shared.f32 [%1], %2; }"
        :: "r"(pred_q), "r"(addr), "f"(v) : "memory");
}

#define LOG2E 1.4426950408889634f

// one LSTM step: quarter matvec + butterfly + act + update (pre added post-bfly)
__device__ __forceinline__ void lstm_step(
    const float* __restrict__ hin, unsigned hout_addr, float pre,
    const ulonglong2 (&wreg)[4][6], float mq,
    int base, int b0, int b1, int q, float& c)
{
    const ulonglong2* hq = (const ulonglong2*)hin;   // hin already offset by 24q
    ulonglong2 h0 = hq[0], h1 = hq[1], h2v = hq[2];
    ulonglong2 h3 = hq[3], h4 = hq[4], h5 = hq[5];

    unsigned long long acc[4][2];
    #pragma unroll
    for (int g = 0; g < 4; g++) { acc[g][0] = 0ull; acc[g][1] = 0ull; }
    #pragma unroll
    for (int g = 0; g < 4; g++) {
        FMA2(acc[g][0], wreg[g][0].x, h0.x, acc[g][0]);
        FMA2(acc[g][1], wreg[g][0].y, h0.y, acc[g][1]);
        FMA2(acc[g][0], wreg[g][1].x, h1.x, acc[g][0]);
        FMA2(acc[g][1], wreg[g][1].y, h1.y, acc[g][1]);
        FMA2(acc[g][0], wreg[g][2].x, h2v.x, acc[g][0]);
        FMA2(acc[g][1], wreg[g][2].y, h2v.y, acc[g][1]);
        FMA2(acc[g][0], wreg[g][3].x, h3.x, acc[g][0]);
        FMA2(acc[g][1], wreg[g][3].y, h3.y, acc[g][1]);
        FMA2(acc[g][0], wreg[g][4].x, h4.x, acc[g][0]);
        FMA2(acc[g][1], wreg[g][4].y, h4.y, acc[g][1]);
        FMA2(acc[g][0], wreg[g][5].x, h5.x, acc[g][0]);
        FMA2(acc[g][1], wreg[g][5].y, h5.y, acc[g][1]);
    }
    float pg[4];
    #pragma unroll
    for (int g = 0; g < 4; g++) {
        unsigned long long s;
        ADD2(s, acc[g][0], acc[g][1]);
        float lo, hi;
        UNPACK2(lo, hi, s);
        pg[g] = lo + hi;
    }

    // butterfly: lane q ends with gate q's full sum; own pre added afterwards
    float keepA = b0 ? pg[1] : pg[0];
    float sendA = b0 ? pg[0] : pg[1];
    float keepB = b0 ? pg[3] : pg[2];
    float sendB = b0 ? pg[2] : pg[3];
    keepA += __shfl_xor_sync(0xffffffffu, sendA, 1);
    keepB += __shfl_xor_sync(0xffffffffu, sendB, 1);
    float keep = b1 ? keepB : keepA;
    float send = b1 ? keepA : keepB;
    float z = keep + __shfl_xor_sync(0xffffffffu, send, 2) + pre;

    float e   = ex2_fast(z);
    float r   = rcp_fast(e + 1.0f);
    float act = fmaf(-mq, r, 1.0f);

    float iv = __shfl_sync(0xffffffffu, act, base);
    float fv = __shfl_sync(0xffffffffu, act, base + 1);
    float gv = __shfl_sync(0xffffffffu, act, base + 2);
    float ov = __shfl_sync(0xffffffffu, act, base + 3);

    c = fmaf(fv, c, iv * gv);
    float e2 = ex2_fast(c * (2.0f * LOG2E));
    float hc = ov * fmaf(-2.0f, rcp_fast(e2 + 1.0f), 1.0f);
    sts_pred(q, hout_addr, hc);   // only sublane 0 stores; 1 wavefront; less drain
}

__global__ void __launch_bounds__(NTHR, 1)
lstm_persistent_kernel(const float* __restrict__ x,
                       const float* __restrict__ w_ih,
                       const float* __restrict__ w_hh,
                       const float* __restrict__ b_ih,
                       const float* __restrict__ b_hh,
                       const float* __restrict__ w_out,
                       const float* __restrict__ b_out,
                       float* __restrict__ out)
{
    __shared__ __align__(16) float x_s[TLEN];
    __shared__ __align__(16) float h_s[2][HDIM];

    const int tid  = threadIdx.x;
    const int b    = blockIdx.x;
    const int wid  = tid >> 5;
    const int lane = tid & 31;

    {
        const float4* xg = (const float4*)(x + (size_t)b * TLEN);
        float4* xs = (float4*)x_s;
        for (int i = tid; i < TLEN / 4; i += NTHR) xs[i] = xg[i];
    }
    if (tid < HDIM) { h_s[0][tid] = 0.0f; h_s[1][tid] = 0.0f; }

    const bool is_gate = (wid < 12);
    const int u = 8 * wid + (lane >> 2);
    const int q = lane & 3;

    ulonglong2 wreg[4][6];
    float wi = 0.0f, bias = 0.0f;
    if (is_gate) {
        #pragma unroll
        for (int g = 0; g < 4; g++) {
            const float sg = (g == 2) ? 2.0f * LOG2E : LOG2E;
            const float4* wr = (const float4*)(w_hh + (size_t)(g * HDIM + u) * HDIM + 24 * q);
            #pragma unroll
            for (int j = 0; j < 6; j++) {
                float4 t = wr[j];
                t.x *= sg; t.y *= sg; t.z *= sg; t.w *= sg;
                ulonglong2 pk;
                memcpy(&pk, &t, 16);
                wreg[g][j] = pk;
            }
        }
        const float sq = (q == 2) ? 2.0f * LOG2E : LOG2E;
        const int row = q * HDIM + u;
        wi   = w_ih[row] * sq;
        bias = (b_ih[row] + b_hh[row]) * sq;
    }
    const float mq = (q == 2) ? 2.0f : 1.0f;
    const int  base = lane & ~3;
    const int  b0 = lane & 1, b1 = lane & 2;

    float* outrow = out + (size_t)b * TLEN;
    const unsigned haddr0 = (unsigned)__cvta_generic_to_shared(&h_s[0][u]);
    const unsigned haddr1 = (unsigned)__cvta_generic_to_shared(&h_s[1][u]);

    __syncthreads();

    if (is_gate) {
        const float* hin0 = h_s[0] + 24 * q;
        const float* hin1 = h_s[1] + 24 * q;
        float c = 0.0f;
        float x0 = x_s[0], x1 = x_s[1];
        #pragma unroll 1
        for (int t = 0; t < TLEN; t += 2) {
            int tn = (t + 2 < TLEN) ? t + 2 : 0;     // clamped prefetch index
            float xn0 = x_s[tn], xn1 = x_s[tn + 1];
            lstm_step(hin0, haddr1, fmaf(x0, wi, bias), wreg, mq, base, b0, b1, q, c);
            cta_bar();
            lstm_step(hin1, haddr0, fmaf(x1, wi, bias), wreg, mq, base, b0, b1, q, c);
            cta_bar();
            x0 = xn0; x1 = xn1;
        }
    } else {
        float wo0 = w_out[lane];
        float wo1 = w_out[lane + 32];
        float wo2 = w_out[lane + 64];
        float bo  = b_out[0];

        cta_bar();
        #pragma unroll 1
        for (int t = 1; t < TLEN; t++) {
            const float* hprev = h_s[t & 1];
            float part = hprev[lane] * wo0 + hprev[lane + 32] * wo1
                       + hprev[lane + 64] * wo2;
            part += __shfl_xor_sync(0xffffffffu, part, 16);
            part += __shfl_xor_sync(0xffffffffu, part, 8);
            part += __shfl_xor_sync(0xffffffffu, part, 4);
            part += __shfl_xor_sync(0xffffffffu, part, 2);
            part += __shfl_xor_sync(0xffffffffu, part, 1);
            if (lane == 0) outrow[t - 1] = part + bo;
            cta_bar();
        }
        const float* hlast = h_s[0];
        float part = hlast[lane] * wo0 + hlast[lane + 32] * wo1
                   + hlast[lane + 64] * wo2;
        part += __shfl_xor_sync(0xffffffffu, part, 16);
        part += __shfl_xor_sync(0xffffffffu, part, 8);
        part += __shfl_xor_sync(0xffffffffu, part, 4);
        part += __shfl_xor_sync(0xffffffffu, part, 2);
        part += __shfl_xor_sync(0xffffffffu, part, 1);
        if (lane == 0) outrow[TLEN - 1] = part + bo;
    }
}

extern "C" void kernel_launch(void* const* d_in, const int* in_sizes, int n_in,
                              void* d_out, int out_size)
{
    const float* x     = (const float*)d_in[0];
    const float* w_ih  = (const float*)d_in[1];
    const float* w_hh  = (const float*)d_in[2];
    const float* b_ih  = (const float*)d_in[3];
    const float* b_hh  = (const float*)d_in[4];
    const float* w_out = (const float*)d_in[5];
    const float* b_out = (const float*)d_in[6];
    float* out = (float*)d_out;

    lstm_persistent_kernel<<<BATCH, NTHR>>>(x, w_ih, w_hh, b_ih, b_hh,
                                            w_out, b_out, out);
}